// round 3
// baseline (speedup 1.0000x reference)
#include <cuda_runtime.h>
#include <cstdint>

#define IMG_W 512
#define IMG_H 512

// ---- f32x2 packed helpers (Blackwell PTX ISA 8.6) ----
__device__ __forceinline__ unsigned long long pack2(float lo, float hi) {
    unsigned long long r;
    asm("mov.b64 %0, {%1, %2};"
        : "=l"(r) : "r"(__float_as_uint(lo)), "r"(__float_as_uint(hi)));
    return r;
}

__device__ __forceinline__ void fma2(unsigned long long& d,
                                     unsigned long long a,
                                     unsigned long long b) {
    asm("fma.rn.f32x2 %0, %1, %2, %0;" : "+l"(d) : "l"(a), "l"(b));
}

__device__ __forceinline__ void unpack2(unsigned long long v, float& lo, float& hi) {
    unsigned int lu, hu;
    asm("mov.b64 {%0, %1}, %2;" : "=r"(lu), "=r"(hu) : "l"(v));
    lo = __uint_as_float(lu);
    hi = __uint_as_float(hu);
}

// Each thread: 4 output rows x 4 output cols.
// Block: 256 threads = 128 col-threads (covering all 512 cols) x 2 row-groups.
// Block tile: 512 cols x 8 rows. Grid: (64 row tiles, 128 images).
__global__ __launch_bounds__(256)
void conv5x5_f32x2_kernel(const float* __restrict__ X,
                          const float* __restrict__ K,
                          float* __restrict__ O) {
    const int tx   = threadIdx.x & 127;        // 0..127 -> column group
    const int tg   = threadIdx.x >> 7;         // 0..1   -> row group in block
    const int col  = tx << 2;                  // output col base (mult of 4)
    const int img  = blockIdx.y;               // 0..127 (B*C)
    const int row0 = (blockIdx.x << 3) + (tg << 2);  // output row base

    // Broadcast-packed kernel weights: wp[kr][kc] = (w, w)
    unsigned long long wp[5][5];
    #pragma unroll
    for (int i = 0; i < 25; i++) {
        const float w = __ldg(K + i);
        wp[i / 5][i % 5] = pack2(w, w);
    }

    const float* in = X + (size_t)img * (IMG_W * IMG_H);

    // acc[ro][0] = outputs (col, col+1); acc[ro][1] = (col+2, col+3)
    unsigned long long acc[4][2];
    #pragma unroll
    for (int ro = 0; ro < 4; ro++) { acc[ro][0] = 0ull; acc[ro][1] = 0ull; }

    #pragma unroll
    for (int lr = 0; lr < 8; lr++) {
        const int r = row0 - 2 + lr;           // input row
        float x0, x1, x2, x3, x4, x5, x6, x7;  // cols col-2 .. col+5
        if (r >= 0 && r < IMG_H) {
            const float* rp = in + (size_t)r * IMG_W;
            float2 lv = (col >= 2)
                ? *reinterpret_cast<const float2*>(rp + col - 2)
                : make_float2(0.f, 0.f);
            float4 mv = *reinterpret_cast<const float4*>(rp + col);
            float2 rv = (col + 4 < IMG_W)
                ? *reinterpret_cast<const float2*>(rp + col + 4)
                : make_float2(0.f, 0.f);
            x0 = lv.x; x1 = lv.y;
            x2 = mv.x; x3 = mv.y; x4 = mv.z; x5 = mv.w;
            x6 = rv.x; x7 = rv.y;
        } else {
            x0 = x1 = x2 = x3 = x4 = x5 = x6 = x7 = 0.f;
        }

        // Sliding pairs: p[i] = (x[i], x[i+1]), i = 0..6
        unsigned long long p[7];
        p[0] = pack2(x0, x1); p[1] = pack2(x1, x2); p[2] = pack2(x2, x3);
        p[3] = pack2(x3, x4); p[4] = pack2(x4, x5); p[5] = pack2(x5, x6);
        p[6] = pack2(x6, x7);

        // Input row r feeds output rows ro with kr = lr - ro in [0,4]
        #pragma unroll
        for (int ro = 0; ro < 4; ro++) {
            const int kr = lr - ro;
            if (kr < 0 || kr > 4) continue;
            #pragma unroll
            for (int kc = 0; kc < 5; kc++) {
                fma2(acc[ro][0], p[kc],     wp[kr][kc]);   // outputs col, col+1
                fma2(acc[ro][1], p[kc + 2], wp[kr][kc]);   // outputs col+2, col+3
            }
        }
    }

    float* op = O + (size_t)img * (IMG_W * IMG_H) + (size_t)row0 * IMG_W + col;
    #pragma unroll
    for (int ro = 0; ro < 4; ro++) {
        float4 v;
        unpack2(acc[ro][0], v.x, v.y);
        unpack2(acc[ro][1], v.z, v.w);
        *reinterpret_cast<float4*>(op + (size_t)ro * IMG_W) = v;
    }
}

extern "C" void kernel_launch(void* const* d_in, const int* in_sizes, int n_in,
                              void* d_out, int out_size) {
    const float* X = (const float*)d_in[0];   // (4,32,512,512) f32
    const float* K = (const float*)d_in[1];   // (5,5) f32
    float* O = (float*)d_out;                 // (4,32,512,512) f32
    (void)in_sizes; (void)n_in; (void)out_size;  // stride=1, padding=2 hardcoded

    dim3 grid(IMG_H / 8, 4 * 32);  // 64 row-tiles x 128 images
    conv5x5_f32x2_kernel<<<grid, 256>>>(X, K, O);
}